// round 2
// baseline (speedup 1.0000x reference)
#include <cuda_runtime.h>
#include <cstdint>

#define B_DIM 32
#define T_DIM 4096
#define M_DIM 256            // GEMM K
#define L_DIM 128            // GEMM N
#define R_DIM (B_DIM * T_DIM * 2)   // 262144 GEMM rows
#define ROW_TILE 128
#define NUM_TILES (R_DIM / ROW_TILE) // 2048
#define K_CHUNK 64
#define N_CHUNKS (M_DIM / K_CHUNK)   // 4
#define A_STRIDE 68          // padded floats per A row (conflict-free frag loads)
#define V_STRIDE 260         // padded floats per v row (conflict-free frag loads)
#define THREADS 256          // 8 warps: 4 (M) x 2 (N)

// Shared memory layout (floats):
//   v_s  : L_DIM * V_STRIDE          = 33280
//   a_s  : 2 * ROW_TILE * A_STRIDE   = 17408
//   w_s  : 128
//   sc_s : 128
#define SMEM_FLOATS (L_DIM * V_STRIDE + 2 * ROW_TILE * A_STRIDE + 128 + 128)
#define SMEM_BYTES (SMEM_FLOATS * 4)

__device__ __forceinline__ uint32_t f2tf32(float f) {
    uint32_t u;
    asm("cvt.rna.tf32.f32 %0, %1;" : "=r"(u) : "f"(f));
    return u;
}

__device__ __forceinline__ void cp_async16(void* s, const void* g) {
    uint32_t sa = (uint32_t)__cvta_generic_to_shared(s);
    asm volatile("cp.async.cg.shared.global [%0], [%1], 16;\n" :: "r"(sa), "l"(g));
}

__device__ __forceinline__ void mma_tf32(float& c0, float& c1, float& c2, float& c3,
                                         uint32_t a0, uint32_t a1, uint32_t a2, uint32_t a3,
                                         uint32_t b0, uint32_t b1) {
    asm volatile(
        "mma.sync.aligned.m16n8k8.row.col.f32.tf32.tf32.f32 "
        "{%0,%1,%2,%3}, {%4,%5,%6,%7}, {%8,%9}, {%0,%1,%2,%3};\n"
        : "+f"(c0), "+f"(c1), "+f"(c2), "+f"(c3)
        : "r"(a0), "r"(a1), "r"(a2), "r"(a3), "r"(b0), "r"(b1));
}

__global__ void __launch_bounds__(THREADS, 1)
topo_attention_kernel(const float* __restrict__ h1,
                      const float* __restrict__ h2,
                      const float* __restrict__ w,
                      const float* __restrict__ v,
                      float* __restrict__ out) {
    extern __shared__ float smem[];
    float* v_s  = smem;
    float* a_s  = smem + L_DIM * V_STRIDE;
    float* w_s  = a_s + 2 * ROW_TILE * A_STRIDE;
    float* sc_s = w_s + 128;

    const int tid  = threadIdx.x;
    const int wid  = tid >> 5;
    const int lane = tid & 31;
    const int warp_m = wid & 3;   // 0..3 -> 32 rows each
    const int warp_n = wid >> 2;  // 0..1 -> 64 cols each
    const int g   = lane >> 2;    // groupID 0..7
    const int tig = lane & 3;     // threadID_in_group 0..3

    // Load w into smem
    if (tid < L_DIM) w_s[tid] = w[tid];
    // Load whole v_tp into smem, converted to tf32 once.
    for (int i = tid; i < L_DIM * M_DIM; i += THREADS) {
        int l = i >> 8;       // / 256
        int m = i & 255;
        v_s[l * V_STRIDE + m] = __uint_as_float(f2tf32(v[i]));
    }
    __syncthreads();

    for (int tile = blockIdx.x; tile < NUM_TILES; tile += gridDim.x) {
        const int base_row = tile * ROW_TILE;

        // zero per-row score accumulator (ordered by the syncthreads below)
        if (tid < 128) sc_s[tid] = 0.0f;

        float acc[2][8][4];
        #pragma unroll
        for (int mt = 0; mt < 2; mt++)
            #pragma unroll
            for (int nt = 0; nt < 8; nt++)
                #pragma unroll
                for (int i = 0; i < 4; i++) acc[mt][nt][i] = 0.0f;

        // ---- prefetch chunk 0 ----
        {
            #pragma unroll
            for (int it = 0; it < 8; ++it) {
                int idx = it * THREADS + tid;      // 0..2047
                int r   = idx >> 4;                // 0..127
                int c4  = idx & 15;                // 0..15 float4 within 64-wide chunk
                int gr  = base_row + r;
                const float* src = ((gr & 1) ? h2 : h1) + ((long)(gr >> 1)) * M_DIM + c4 * 4;
                cp_async16(&a_s[r * A_STRIDE + c4 * 4], src);
            }
            asm volatile("cp.async.commit_group;\n");
        }

        #pragma unroll
        for (int chunk = 0; chunk < N_CHUNKS; ++chunk) {
            // prefetch next chunk into the other buffer
            if (chunk + 1 < N_CHUNKS) {
                int nbuf = (chunk + 1) & 1;
                #pragma unroll
                for (int it = 0; it < 8; ++it) {
                    int idx = it * THREADS + tid;
                    int r   = idx >> 4;
                    int c4  = idx & 15;
                    int gr  = base_row + r;
                    const float* src = ((gr & 1) ? h2 : h1) + ((long)(gr >> 1)) * M_DIM
                                       + (chunk + 1) * K_CHUNK + c4 * 4;
                    cp_async16(&a_s[nbuf * ROW_TILE * A_STRIDE + r * A_STRIDE + c4 * 4], src);
                }
                asm volatile("cp.async.commit_group;\n");
                asm volatile("cp.async.wait_group 1;\n");
            } else {
                asm volatile("cp.async.wait_group 0;\n");
            }
            __syncthreads();

            const float* As = a_s + (chunk & 1) * ROW_TILE * A_STRIDE;
            const int kg_base = chunk * K_CHUNK;

            #pragma unroll
            for (int ks = 0; ks < K_CHUNK / 8; ++ks) {
                const int k0 = ks * 8;
                uint32_t afr[2][4];
                #pragma unroll
                for (int mt = 0; mt < 2; mt++) {
                    int rb = warp_m * 32 + mt * 16;
                    afr[mt][0] = f2tf32(As[(rb + g)     * A_STRIDE + k0 + tig]);
                    afr[mt][1] = f2tf32(As[(rb + 8 + g) * A_STRIDE + k0 + tig]);
                    afr[mt][2] = f2tf32(As[(rb + g)     * A_STRIDE + k0 + tig + 4]);
                    afr[mt][3] = f2tf32(As[(rb + 8 + g) * A_STRIDE + k0 + tig + 4]);
                }
                uint32_t bfr[8][2];
                #pragma unroll
                for (int nt = 0; nt < 8; nt++) {
                    int l = warp_n * 64 + nt * 8 + g;
                    bfr[nt][0] = __float_as_uint(v_s[l * V_STRIDE + kg_base + k0 + tig]);
                    bfr[nt][1] = __float_as_uint(v_s[l * V_STRIDE + kg_base + k0 + tig + 4]);
                }
                #pragma unroll
                for (int mt = 0; mt < 2; mt++)
                    #pragma unroll
                    for (int nt = 0; nt < 8; nt++)
                        mma_tf32(acc[mt][nt][0], acc[mt][nt][1], acc[mt][nt][2], acc[mt][nt][3],
                                 afr[mt][0], afr[mt][1], afr[mt][2], afr[mt][3],
                                 bfr[nt][0], bfr[nt][1]);
            }
            __syncthreads();
        }

        // ---- epilogue: tanh, weight-dot, per-row reduce ----
        float part[4] = {0.f, 0.f, 0.f, 0.f}; // rows: warp_m*32 + mt*16 + h*8 + g
        #pragma unroll
        for (int mt = 0; mt < 2; mt++) {
            #pragma unroll
            for (int nt = 0; nt < 8; nt++) {
                int l0 = warp_n * 64 + nt * 8 + tig * 2;
                float w0 = w_s[l0], w1 = w_s[l0 + 1];
                part[mt * 2 + 0] += w0 * tanhf(acc[mt][nt][0]) + w1 * tanhf(acc[mt][nt][1]);
                part[mt * 2 + 1] += w0 * tanhf(acc[mt][nt][2]) + w1 * tanhf(acc[mt][nt][3]);
            }
        }
        // reduce over the 4 lanes of each group (tig axis)
        #pragma unroll
        for (int i = 0; i < 4; i++) {
            part[i] += __shfl_xor_sync(0xffffffffu, part[i], 1);
            part[i] += __shfl_xor_sync(0xffffffffu, part[i], 2);
        }
        if (tig == 0) {
            #pragma unroll
            for (int i = 0; i < 4; i++) {
                int row = warp_m * 32 + (i >> 1) * 16 + (i & 1) * 8 + g;
                atomicAdd(&sc_s[row], part[i]);
            }
        }
        __syncthreads();

        // ---- 2-way softmax + scattered write ----
        if (tid < 64) {
            int p_local = tid;
            float s0 = sc_s[2 * p_local];
            float s1 = sc_s[2 * p_local + 1];
            int P = tile * 64 + p_local;        // global (b*T + t)
            int b = P >> 12;                     // / 4096
            int t = P & 4095;
            float a0 = 1.0f / (1.0f + __expf(s1 - s0));
            out[((b * 2) + 0) * T_DIM + t] = a0;
            out[((b * 2) + 1) * T_DIM + t] = 1.0f - a0;
        }
        __syncthreads(); // protect sc_s before next tile re-zeroes it
    }
}

extern "C" void kernel_launch(void* const* d_in, const int* in_sizes, int n_in,
                              void* d_out, int out_size) {
    const float* h1 = (const float*)d_in[0];
    const float* h2 = (const float*)d_in[1];
    const float* w  = (const float*)d_in[2];
    const float* v  = (const float*)d_in[3];
    float* out = (float*)d_out;

    cudaFuncSetAttribute(topo_attention_kernel,
                         cudaFuncAttributeMaxDynamicSharedMemorySize, SMEM_BYTES);

    int nsm = 148;
    if (cudaDeviceGetAttribute(&nsm, cudaDevAttrMultiProcessorCount, 0) != cudaSuccess || nsm <= 0)
        nsm = 148;

    topo_attention_kernel<<<nsm, THREADS, SMEM_BYTES>>>(h1, h2, w, v, out);
}

// round 4
// speedup vs baseline: 1.0642x; 1.0642x over previous
#include <cuda_runtime.h>
#include <cstdint>

#define T_DIM 4096
#define NUM_TILES 2048
#define THREADS 512

// ---- shared memory layout (bytes) ----
// VF: v_tp packed in B-fragment order: [nb(16)][ks(32)][lane(32)][2 floats]
#define VF_OFF 0
// AF: A chunk (128 rows x 64 k) packed in A-fragment order:
//     [mb(8)][ks(8)][cell(32) = lane^ks][4 floats(q)]
#define AF_OFF 131072
#define W_OFF  163840
#define SC_OFF 164352
#define SMEM_BYTES 164864

__device__ __forceinline__ uint32_t f2tf32(float f) {
    uint32_t u;
    asm("cvt.rna.tf32.f32 %0, %1;" : "=r"(u) : "f"(f));
    return u;
}

__device__ __forceinline__ void sts32(uint32_t addr, uint32_t v) {
    asm volatile("st.shared.b32 [%0], %1;" :: "r"(addr), "r"(v) : "memory");
}

__device__ __forceinline__ void lds128(uint32_t* r, uint32_t addr) {
    asm volatile("ld.shared.v4.b32 {%0,%1,%2,%3}, [%4];"
                 : "=r"(r[0]), "=r"(r[1]), "=r"(r[2]), "=r"(r[3]) : "r"(addr));
}

__device__ __forceinline__ void lds64(uint32_t* r, uint32_t addr) {
    asm volatile("ld.shared.v2.b32 {%0,%1}, [%2];"
                 : "=r"(r[0]), "=r"(r[1]) : "r"(addr));
}

__device__ __forceinline__ void mma_tf32(float* c, const uint32_t* a, const uint32_t* b) {
    asm volatile(
        "mma.sync.aligned.m16n8k8.row.col.f32.tf32.tf32.f32 "
        "{%0,%1,%2,%3}, {%4,%5,%6,%7}, {%8,%9}, {%0,%1,%2,%3};\n"
        : "+f"(c[0]), "+f"(c[1]), "+f"(c[2]), "+f"(c[3])
        : "r"(a[0]), "r"(a[1]), "r"(a[2]), "r"(a[3]), "r"(b[0]), "r"(b[1]));
}

__device__ __forceinline__ void ldg4(float4* rg, int gc,
                                     const float* h1, const float* h2,
                                     int tid, int bx, int grid) {
    int tile = bx + (gc >> 2) * grid;
    int c = gc & 3;
    int base_row = tile * 128;
    #pragma unroll
    for (int it = 0; it < 4; ++it) {
        int idx = it * THREADS + tid;     // 0..2047
        int r = idx >> 4;                 // 0..127
        int c4 = idx & 15;                // float4 within 64-float chunk
        int gr = base_row + r;
        const float4* src = (const float4*)((gr & 1) ? h2 : h1)
                            + (size_t)(gr >> 1) * 64 + c * 16 + c4;
        rg[it] = __ldg(src);
    }
}

__global__ void __launch_bounds__(THREADS, 1)
topo_attention_v2(const float* __restrict__ h1,
                  const float* __restrict__ h2,
                  const float* __restrict__ w,
                  const float* __restrict__ v,
                  float* __restrict__ out) {
    extern __shared__ char smem[];
    uint32_t smem_u32;
    asm("{ .reg .u64 t; cvta.to.shared.u64 t, %1; cvt.u32.u64 %0, t; }"
        : "=r"(smem_u32) : "l"(smem));
    float* w_s  = (float*)(smem + W_OFF);
    float* sc_s = (float*)(smem + SC_OFF);

    const int tid  = threadIdx.x;
    const int wid  = tid >> 5;
    const int lane = tid & 31;
    const int warp_m = wid & 3;    // 4 row groups of 32
    const int warp_n = wid >> 2;   // 4 col groups of 32
    const int g   = lane >> 2;
    const int tig = lane & 3;
    const int bx = blockIdx.x;
    const int grid = gridDim.x;

    // ---- prologue: pack v_tp into B-fragment layout (tf32), load w ----
    for (int i = tid; i < 32768; i += THREADS) {
        int l = i >> 8;           // 0..127 (N index)
        int m = i & 255;          // 0..255 (K index)
        int nb = l >> 3, gg = l & 7;
        int ks = m >> 3, tg = m & 3, half = (m >> 2) & 1;
        uint32_t off = VF_OFF + ((((nb * 32 + ks) * 32) + (gg * 4 + tg)) * 2 + half) * 4;
        sts32(smem_u32 + off, f2tf32(v[i]));
    }
    if (tid < 128) w_s[tid] = w[tid];
    __syncthreads();

    const int n_iter = (NUM_TILES - bx + grid - 1) / grid;
    const int NC = n_iter * 4;

    const uint32_t va = smem_u32 + AF_OFF + warp_m * 8192;
    const uint32_t vb = smem_u32 + VF_OFF + warp_n * 32768 + lane * 8;

    float4 rg[4];
    ldg4(rg, 0, h1, h2, tid, bx, grid);

    for (int e = 0; e < n_iter; ++e) {
        if (tid < 128) sc_s[tid] = 0.0f;

        float acc[2][4][4];
        #pragma unroll
        for (int mt = 0; mt < 2; mt++)
            #pragma unroll
            for (int nt = 0; nt < 4; nt++)
                #pragma unroll
                for (int i = 0; i < 4; i++) acc[mt][nt][i] = 0.0f;

        for (int c = 0; c < 4; ++c) {
            int gc = e * 4 + c;
            __syncthreads();   // previous MMA consumers done with AF buffer
            // ---- STS chunk (convert to tf32, fragment-packed, XOR swizzle) ----
            #pragma unroll
            for (int it = 0; it < 4; ++it) {
                int idx = it * THREADS + tid;
                int r = idx >> 4;
                int c4 = idx & 15;
                int mb = r >> 4, R = r & 15;
                int ks = c4 >> 1, half = c4 & 1;
                uint32_t q = (uint32_t)((R >> 3) | (half << 1));
                uint32_t base = smem_u32 + AF_OFF + mb * 4096 + ks * 512 + q * 4;
                uint32_t lb = (uint32_t)((R & 7) << 2);
                float4 f = rg[it];
                sts32(base + (((lb | 0u) ^ ks) << 4), f2tf32(f.x));
                sts32(base + (((lb | 1u) ^ ks) << 4), f2tf32(f.y));
                sts32(base + (((lb | 2u) ^ ks) << 4), f2tf32(f.z));
                sts32(base + (((lb | 3u) ^ ks) << 4), f2tf32(f.w));
            }
            __syncthreads();   // chunk visible
            if (gc + 1 < NC) ldg4(rg, gc + 1, h1, h2, tid, bx, grid);  // overlap w/ MMA

            // ---- MMA over this chunk ----
            #pragma unroll
            for (int ks = 0; ks < 8; ++ks) {
                uint32_t lx = (uint32_t)((lane ^ ks) << 4);
                uint32_t a0[4], a1[4];
                lds128(a0, va + ks * 512 + lx);
                lds128(a1, va + 4096 + ks * 512 + lx);
                int ksg = c * 8 + ks;
                uint32_t b[4][2];
                #pragma unroll
                for (int nt = 0; nt < 4; ++nt)
                    lds64(b[nt], vb + nt * 8192 + ksg * 256);
                #pragma unroll
                for (int nt = 0; nt < 4; ++nt) {
                    mma_tf32(acc[0][nt], a0, b[nt]);
                    mma_tf32(acc[1][nt], a1, b[nt]);
                }
            }
        }

        // ---- epilogue: tanh, w-dot, per-row reduce ----
        float part[4] = {0.f, 0.f, 0.f, 0.f};
        #pragma unroll
        for (int mt = 0; mt < 2; mt++) {
            #pragma unroll
            for (int nt = 0; nt < 4; nt++) {
                int l0 = warp_n * 32 + nt * 8 + tig * 2;
                float w0 = w_s[l0], w1 = w_s[l0 + 1];
                part[mt * 2 + 0] += w0 * tanhf(acc[mt][nt][0]) + w1 * tanhf(acc[mt][nt][1]);
                part[mt * 2 + 1] += w0 * tanhf(acc[mt][nt][2]) + w1 * tanhf(acc[mt][nt][3]);
            }
        }
        #pragma unroll
        for (int i = 0; i < 4; i++) {
            part[i] += __shfl_xor_sync(0xffffffffu, part[i], 1);
            part[i] += __shfl_xor_sync(0xffffffffu, part[i], 2);
        }
        if (tig == 0) {
            #pragma unroll
            for (int i = 0; i < 4; i++) {
                int row = warp_m * 32 + (i >> 1) * 16 + (i & 1) * 8 + g;
                atomicAdd(&sc_s[row], part[i]);
            }
        }
        __syncthreads();

        // ---- 2-way softmax + scattered write ----
        if (tid < 64) {
            int tile = bx + e * grid;
            float s0 = sc_s[2 * tid];
            float s1 = sc_s[2 * tid + 1];
            int P = tile * 64 + tid;              // global (b*T + t)
            int b = P >> 12;
            int t = P & 4095;
            float a0 = 1.0f / (1.0f + __expf(s1 - s0));
            out[((b * 2) + 0) * T_DIM + t] = a0;
            out[((b * 2) + 1) * T_DIM + t] = 1.0f - a0;
        }
        __syncthreads();   // protect sc_s before next tile re-zeroes it
    }
}

extern "C" void kernel_launch(void* const* d_in, const int* in_sizes, int n_in,
                              void* d_out, int out_size) {
    const float* h1 = (const float*)d_in[0];
    const float* h2 = (const float*)d_in[1];
    const float* w  = (const float*)d_in[2];
    const float* v  = (const float*)d_in[3];
    float* out = (float*)d_out;

    cudaFuncSetAttribute(topo_attention_v2,
                         cudaFuncAttributeMaxDynamicSharedMemorySize, SMEM_BYTES);

    int nsm = 148;
    if (cudaDeviceGetAttribute(&nsm, cudaDevAttrMultiProcessorCount, 0) != cudaSuccess || nsm <= 0)
        nsm = 148;

    topo_attention_v2<<<nsm, THREADS, SMEM_BYTES>>>(h1, h2, w, v, out);
}

// round 5
// speedup vs baseline: 1.1713x; 1.1006x over previous
#include <cuda_runtime.h>
#include <cstdint>

#define T_DIM 4096
#define NSUPER 1024          // 2048 tiles / 2 tiles per super
#define THREADS 512

// ---- shared memory layout (bytes) ----
// VF: v_tp packed fragment-major: [ksg(32)][np(8)][lane(32)][16B: nbE_h0,nbE_h1,nbO_h0,nbO_h1]
#define VF_OFF 0
#define VF_BYTES 131072
// A: double-buffered 2-tile chunk: [buf(2)][pt(2)][row(128)][swizzled 8x16B cells]
#define A_OFF  131072
#define A_BUF_BYTES 32768
#define W_OFF  196608
#define SC_OFF 197120
#define SMEM_BYTES 198144

__device__ __forceinline__ uint32_t f2tf32(float f) {
    uint32_t u;
    asm("cvt.rna.tf32.f32 %0, %1;" : "=r"(u) : "f"(f));
    return u;
}

__device__ __forceinline__ void sts32(uint32_t addr, uint32_t v) {
    asm volatile("st.shared.b32 [%0], %1;" :: "r"(addr), "r"(v) : "memory");
}

__device__ __forceinline__ void sts128(uint32_t addr, uint32_t a, uint32_t b, uint32_t c, uint32_t d) {
    asm volatile("st.shared.v4.b32 [%0], {%1,%2,%3,%4};"
                 :: "r"(addr), "r"(a), "r"(b), "r"(c), "r"(d) : "memory");
}

__device__ __forceinline__ void lds128(uint32_t* r, uint32_t addr) {
    asm volatile("ld.shared.v4.b32 {%0,%1,%2,%3}, [%4];"
                 : "=r"(r[0]), "=r"(r[1]), "=r"(r[2]), "=r"(r[3]) : "r"(addr));
}

__device__ __forceinline__ void ldsm4(uint32_t* r, uint32_t addr) {
    asm volatile("ldmatrix.sync.aligned.m8n8.x4.shared.b16 {%0,%1,%2,%3}, [%4];"
                 : "=r"(r[0]), "=r"(r[1]), "=r"(r[2]), "=r"(r[3]) : "r"(addr));
}

__device__ __forceinline__ void mma_tf32(float* c, const uint32_t* a, uint32_t b0, uint32_t b1) {
    asm volatile(
        "mma.sync.aligned.m16n8k8.row.col.f32.tf32.tf32.f32 "
        "{%0,%1,%2,%3}, {%4,%5,%6,%7}, {%8,%9}, {%0,%1,%2,%3};\n"
        : "+f"(c[0]), "+f"(c[1]), "+f"(c[2]), "+f"(c[3])
        : "r"(a[0]), "r"(a[1]), "r"(a[2]), "r"(a[3]), "r"(b0), "r"(b1));
}

// load chunk gc (4 float4/thread) into rg
__device__ __forceinline__ void ldg_chunk(float4* rg, int gc,
                                          const float* h1, const float* h2,
                                          int tid, int bx, int grid) {
    int sp = bx + (gc >> 3) * grid;
    int c = gc & 7;
    #pragma unroll
    for (int it = 0; it < 4; ++it) {
        int pt = it >> 1;
        int idx2 = (it & 1) * THREADS + tid;     // 0..1023
        int r = idx2 >> 3;                       // 0..127
        int cell = idx2 & 7;                     // 16B cell in 32-float row
        int gr = sp * 256 + pt * 128 + r;
        const float4* src = (const float4*)((gr & 1) ? h2 : h1)
                            + (size_t)(gr >> 1) * 64 + c * 8 + cell;
        rg[it] = __ldg(src);
    }
}

// store staged chunk (tf32-converted) into buffer (gc&1), swizzled row-major
__device__ __forceinline__ void sts_chunk(const float4* rg, int gc, int tid, uint32_t smem_u32) {
    uint32_t base = smem_u32 + A_OFF + (uint32_t)(gc & 1) * A_BUF_BYTES;
    #pragma unroll
    for (int it = 0; it < 4; ++it) {
        int pt = it >> 1;
        int idx2 = (it & 1) * THREADS + tid;
        int r = idx2 >> 3;
        int cell = idx2 & 7;
        uint32_t addr = base + (uint32_t)(pt * 16384 + r * 128 + (((cell ^ (r & 7))) << 4));
        sts128(addr, f2tf32(rg[it].x), f2tf32(rg[it].y), f2tf32(rg[it].z), f2tf32(rg[it].w));
    }
}

__global__ void __launch_bounds__(THREADS, 1)
topo_attention_v3(const float* __restrict__ h1,
                  const float* __restrict__ h2,
                  const float* __restrict__ w,
                  const float* __restrict__ v,
                  float* __restrict__ out) {
    extern __shared__ char smem[];
    uint32_t smem_u32;
    asm("{ .reg .u64 t; cvta.to.shared.u64 t, %1; cvt.u32.u64 %0, t; }"
        : "=r"(smem_u32) : "l"(smem));
    float* w_s  = (float*)(smem + W_OFF);
    float* sc_s = (float*)(smem + SC_OFF);

    const int tid  = threadIdx.x;
    const int wid  = tid >> 5;
    const int lane = tid & 31;
    const int warp_m = wid & 3;     // 4 row groups of 32 (per tile)
    const int warp_n = wid >> 2;    // 4 col groups of 32
    const int g   = lane >> 2;
    const int tig = lane & 3;
    const int bx = blockIdx.x;
    const int grid = gridDim.x;

    // lane constants for ldmatrix addressing
    const int q     = lane >> 3;        // 0..3 : ldsm tile
    const int rloc  = lane & 7;
    const int khalf = q >> 1;
    const uint32_t rh4 = (uint32_t)((rloc & 6) << 4);

    // ---- prologue: pack v_tp into B-fragment layout (tf32), load w, zero sc ----
    for (int i = tid; i < 32768; i += THREADS) {
        int l = i >> 8;           // 0..127 (N index)
        int m = i & 255;          // 0..255 (K index)
        int nb = l >> 3, gg = l & 7;
        int ksg = m >> 3, tg = m & 3, half = (m >> 2) & 1;
        int lidx = gg * 4 + tg;
        uint32_t off = (uint32_t)(ksg * 4096 + (nb >> 1) * 512 + lidx * 16 + (nb & 1) * 8 + half * 4);
        sts32(smem_u32 + VF_OFF + off, f2tf32(v[i]));
    }
    if (tid < 128) w_s[tid] = w[tid];
    if (tid < 256) sc_s[tid] = 0.0f;
    __syncthreads();

    // A fragment base addresses (per pt, mt) for ldmatrix
    uint32_t abase[2][2];
    #pragma unroll
    for (int pt = 0; pt < 2; ++pt)
        #pragma unroll
        for (int mt = 0; mt < 2; ++mt)
            abase[pt][mt] = smem_u32 + A_OFF +
                (uint32_t)(pt * 16384 + (warp_m * 32 + mt * 16 + (q & 1) * 8 + rloc) * 128 +
                           ((khalf ^ (rloc & 1)) << 4));
    const uint32_t vbase = smem_u32 + VF_OFF + (uint32_t)(warp_n * 2 * 512 + lane * 16);

    int nsup = 0;
    for (int sp = bx; sp < NSUPER; sp += grid) nsup++;
    const int NC = nsup * 8;

    float acc[2][2][4][4];
    #pragma unroll
    for (int pt = 0; pt < 2; pt++)
        #pragma unroll
        for (int mt = 0; mt < 2; mt++)
            #pragma unroll
            for (int nt = 0; nt < 4; nt++)
                #pragma unroll
                for (int i = 0; i < 4; i++) acc[pt][mt][nt][i] = 0.0f;

    float4 rg[4];
    ldg_chunk(rg, 0, h1, h2, tid, bx, grid);
    sts_chunk(rg, 0, tid, smem_u32);
    if (NC > 1) ldg_chunk(rg, 1, h1, h2, tid, bx, grid);

    for (int gc = 0; gc < NC; ++gc) {
        __syncthreads();   // MMA(gc-1) done (frees buf (gc+1)&1); STS(gc) visible
        if (gc + 1 < NC) sts_chunk(rg, gc + 1, tid, smem_u32);
        if (gc + 2 < NC) ldg_chunk(rg, gc + 2, h1, h2, tid, bx, grid);

        // ---- MMA over chunk gc (K=32 -> 4 k-slices) ----
        const uint32_t bufoff = (uint32_t)(gc & 1) * A_BUF_BYTES;
        const int c = gc & 7;
        #pragma unroll
        for (int ks = 0; ks < 4; ++ks) {
            uint32_t b0[4], b1[4];
            uint32_t vaddr = vbase + (uint32_t)((c * 4 + ks) * 4096);
            lds128(b0, vaddr);
            lds128(b1, vaddr + 512);
            uint32_t tx = ((uint32_t)(ks << 5)) ^ rh4;
            #pragma unroll
            for (int pt = 0; pt < 2; ++pt) {
                #pragma unroll
                for (int mt = 0; mt < 2; ++mt) {
                    uint32_t a[4];
                    ldsm4(a, abase[pt][mt] + bufoff + tx);
                    mma_tf32(acc[pt][mt][0], a, b0[0], b0[1]);
                    mma_tf32(acc[pt][mt][1], a, b0[2], b0[3]);
                    mma_tf32(acc[pt][mt][2], a, b1[0], b1[1]);
                    mma_tf32(acc[pt][mt][3], a, b1[2], b1[3]);
                }
            }
        }

        if ((gc & 7) == 7) {
            // ---- epilogue for super sp = bx + (gc>>3)*grid ----
            int sp = bx + (gc >> 3) * grid;
            #pragma unroll
            for (int pt = 0; pt < 2; ++pt) {
                float part[4] = {0.f, 0.f, 0.f, 0.f};
                #pragma unroll
                for (int mt = 0; mt < 2; mt++) {
                    #pragma unroll
                    for (int nt = 0; nt < 4; nt++) {
                        int l0 = warp_n * 32 + nt * 8 + tig * 2;
                        float w0 = w_s[l0], w1 = w_s[l0 + 1];
                        part[mt * 2 + 0] += w0 * tanhf(acc[pt][mt][nt][0]) + w1 * tanhf(acc[pt][mt][nt][1]);
                        part[mt * 2 + 1] += w0 * tanhf(acc[pt][mt][nt][2]) + w1 * tanhf(acc[pt][mt][nt][3]);
                        #pragma unroll
                        for (int i = 0; i < 4; i++) acc[pt][mt][nt][i] = 0.0f;
                    }
                }
                #pragma unroll
                for (int i = 0; i < 4; i++) {
                    part[i] += __shfl_xor_sync(0xffffffffu, part[i], 1);
                    part[i] += __shfl_xor_sync(0xffffffffu, part[i], 2);
                }
                if (tig == 0) {
                    #pragma unroll
                    for (int i = 0; i < 4; i++) {
                        int row = pt * 128 + warp_m * 32 + (i >> 1) * 16 + (i & 1) * 8 + g;
                        atomicAdd(&sc_s[row], part[i]);
                    }
                }
            }
            __syncthreads();   // all atomicAdds visible
            if (tid < 128) {
                float s0 = sc_s[2 * tid];
                float s1 = sc_s[2 * tid + 1];
                sc_s[2 * tid] = 0.0f;
                sc_s[2 * tid + 1] = 0.0f;
                int P = sp * 128 + tid;            // global (b*T + t)
                int b = P >> 12;
                int t = P & 4095;
                float a0 = 1.0f / (1.0f + __expf(s1 - s0));
                out[((b * 2) + 0) * T_DIM + t] = a0;
                out[((b * 2) + 1) * T_DIM + t] = 1.0f - a0;
            }
        }
    }
}

extern "C" void kernel_launch(void* const* d_in, const int* in_sizes, int n_in,
                              void* d_out, int out_size) {
    const float* h1 = (const float*)d_in[0];
    const float* h2 = (const float*)d_in[1];
    const float* w  = (const float*)d_in[2];
    const float* v  = (const float*)d_in[3];
    float* out = (float*)d_out;

    cudaFuncSetAttribute(topo_attention_v3,
                         cudaFuncAttributeMaxDynamicSharedMemorySize, SMEM_BYTES);

    int nsm = 148;
    if (cudaDeviceGetAttribute(&nsm, cudaDevAttrMultiProcessorCount, 0) != cudaSuccess || nsm <= 0)
        nsm = 148;

    topo_attention_v3<<<nsm, THREADS, SMEM_BYTES>>>(h1, h2, w, v, out);
}

// round 10
// speedup vs baseline: 2.0083x; 1.7145x over previous
#include <cuda_runtime.h>
#include <cuda_fp16.h>
#include <cstdint>

#define T_DIM 4096
#define NUM_TILES 2048
#define THREADS 256

// ---- shared memory layout (bytes) ----
#define VF_OFF 0             // v_tp fp16 fragment-packed: [ksg(16)][np(8)][lane(32)][16B]
#define A_OFF  65536         // A chunk double-buffered: [buf(2)][row(128)][128B swizzled]
#define A_BUF_BYTES 16384
#define W_OFF  98304
#define SC_OFF 98816
#define SMEM_BYTES 99328

__device__ __forceinline__ uint32_t pack2h(float lo, float hi) {
    uint32_t r;
    asm("cvt.rn.f16x2.f32 %0, %1, %2;" : "=r"(r) : "f"(hi), "f"(lo));
    return r;
}

__device__ __forceinline__ float tanh_fast(float x) {
    float r;
    asm("tanh.approx.f32 %0, %1;" : "=f"(r) : "f"(x));
    return r;
}

__device__ __forceinline__ void sts32(uint32_t addr, uint32_t v) {
    asm volatile("st.shared.b32 [%0], %1;" :: "r"(addr), "r"(v) : "memory");
}

__device__ __forceinline__ void sts64(uint32_t addr, uint32_t a, uint32_t b) {
    asm volatile("st.shared.v2.b32 [%0], {%1,%2};" :: "r"(addr), "r"(a), "r"(b) : "memory");
}

__device__ __forceinline__ void lds128(uint32_t* r, uint32_t addr) {
    asm volatile("ld.shared.v4.b32 {%0,%1,%2,%3}, [%4];"
                 : "=r"(r[0]), "=r"(r[1]), "=r"(r[2]), "=r"(r[3]) : "r"(addr));
}

__device__ __forceinline__ void ldsm4(uint32_t* r, uint32_t addr) {
    asm volatile("ldmatrix.sync.aligned.m8n8.x4.shared.b16 {%0,%1,%2,%3}, [%4];"
                 : "=r"(r[0]), "=r"(r[1]), "=r"(r[2]), "=r"(r[3]) : "r"(addr));
}

__device__ __forceinline__ void mma16(float* c, const uint32_t* a, uint32_t b0, uint32_t b1) {
    asm volatile(
        "mma.sync.aligned.m16n8k16.row.col.f32.f16.f16.f32 "
        "{%0,%1,%2,%3}, {%4,%5,%6,%7}, {%8,%9}, {%0,%1,%2,%3};\n"
        : "+f"(c[0]), "+f"(c[1]), "+f"(c[2]), "+f"(c[3])
        : "r"(a[0]), "r"(a[1]), "r"(a[2]), "r"(a[3]), "r"(b0), "r"(b1));
}

// load chunk gc (8 float4/thread): tile = bx + (gc>>2)*grid, k-chunk = gc&3 (64 floats)
__device__ __forceinline__ void ldg_chunk(float4* rg, int gc,
                                          const float* h1, const float* h2,
                                          int tid, int bx, int grid) {
    int tile = bx + (gc >> 2) * grid;
    int c = gc & 3;
    #pragma unroll
    for (int it = 0; it < 8; ++it) {
        int idx = it * THREADS + tid;      // 0..2047
        int row = idx >> 4;                // 0..127
        int cell = idx & 15;               // float4 cell within 64-float chunk
        int gr = tile * 128 + row;
        const float4* src = (const float4*)((gr & 1) ? h2 : h1)
                            + (size_t)(gr >> 1) * 64 + c * 16 + cell;
        rg[it] = __ldg(src);
    }
}

// convert to fp16 and store into buffer (gc&1); row = 128B of halves, XOR-swizzled 16B cells
__device__ __forceinline__ void sts_chunk(const float4* rg, int gc, int tid, uint32_t smem_u32) {
    uint32_t base = smem_u32 + A_OFF + (uint32_t)(gc & 1) * A_BUF_BYTES;
    #pragma unroll
    for (int it = 0; it < 8; ++it) {
        int idx = it * THREADS + tid;
        int row = idx >> 4;
        int cf = idx & 15;
        int h = cf >> 1, lowh = cf & 1;
        uint32_t addr = base + (uint32_t)(row * 128 + ((h ^ (row & 7)) << 4) + lowh * 8);
        sts64(addr, pack2h(rg[it].x, rg[it].y), pack2h(rg[it].z, rg[it].w));
    }
}

__global__ void __launch_bounds__(THREADS, 2)
topo_attention_v4(const float* __restrict__ h1,
                  const float* __restrict__ h2,
                  const float* __restrict__ w,
                  const float* __restrict__ v,
                  float* __restrict__ out) {
    extern __shared__ char smem[];
    uint32_t smem_u32;
    asm("{ .reg .u64 t; cvta.to.shared.u64 t, %1; cvt.u32.u64 %0, t; }"
        : "=r"(smem_u32) : "l"(smem));
    float* w_s  = (float*)(smem + W_OFF);
    float* sc_s = (float*)(smem + SC_OFF);

    const int tid  = threadIdx.x;
    const int wid  = tid >> 5;
    const int lane = tid & 31;
    const int warp_m = wid >> 2;    // 2 groups of m64
    const int warp_n = wid & 3;     // 4 groups of n32
    const int g   = lane >> 2;
    const int tig = lane & 3;
    const int bx = blockIdx.x;
    const int grid = gridDim.x;

    // ---- prologue: pack v_tp into fp16 B-fragment layout, load w, zero sc ----
    for (int i = tid * 4; i < 32768; i += THREADS * 4) {
        float4 vv = *(const float4*)(v + i);
        int l = i >> 8, m = i & 255;
        int nb = l >> 3, gg = l & 7;
        int ksg = m >> 4, kin = m & 15;
        int half = kin >> 3, tg = (kin & 7) >> 1;
        uint32_t addr = smem_u32 + VF_OFF +
            (uint32_t)(ksg * 4096 + (nb >> 1) * 512 + (gg * 4 + tg) * 16 + (nb & 1) * 8 + half * 4);
        sts32(addr, pack2h(vv.x, vv.y));
        sts32(addr + 16, pack2h(vv.z, vv.w));
    }
    if (tid < 128) { w_s[tid] = w[tid]; sc_s[tid] = 0.0f; }
    __syncthreads();

    // ldmatrix lane addressing for A fragments
    const int q = lane >> 3, rloc = lane & 7, khalf = q >> 1;
    uint32_t abase[4];
    int hb[4];
    #pragma unroll
    for (int mt = 0; mt < 4; ++mt) {
        int row = warp_m * 64 + mt * 16 + (q & 1) * 8 + rloc;
        abase[mt] = smem_u32 + A_OFF + (uint32_t)(row * 128);
        hb[mt] = khalf ^ (row & 7);
    }
    const uint32_t vbase = smem_u32 + VF_OFF + (uint32_t)(warp_n * 1024 + lane * 16);

    int ntile = 0;
    for (int t = bx; t < NUM_TILES; t += grid) ntile++;
    const int NC = ntile * 4;

    float acc[4][4][4];
    #pragma unroll
    for (int mt = 0; mt < 4; mt++)
        #pragma unroll
        for (int nt = 0; nt < 4; nt++)
            #pragma unroll
            for (int i = 0; i < 4; i++) acc[mt][nt][i] = 0.0f;

    float4 rg[8];
    ldg_chunk(rg, 0, h1, h2, tid, bx, grid);
    sts_chunk(rg, 0, tid, smem_u32);
    if (NC > 1) ldg_chunk(rg, 1, h1, h2, tid, bx, grid);

    for (int gc = 0; gc < NC; ++gc) {
        __syncthreads();   // MMA(gc-1) done; STS(gc) visible
        if (gc + 1 < NC) sts_chunk(rg, gc + 1, tid, smem_u32);
        if (gc + 2 < NC) ldg_chunk(rg, gc + 2, h1, h2, tid, bx, grid);

        const uint32_t bufoff = (uint32_t)(gc & 1) * A_BUF_BYTES;
        const int cc = (gc & 3) * 4;
        #pragma unroll
        for (int ks = 0; ks < 4; ++ks) {
            uint32_t bb0[4], bb1[4];
            uint32_t vaddr = vbase + (uint32_t)((cc + ks) * 4096);
            lds128(bb0, vaddr);
            lds128(bb1, vaddr + 512);
            #pragma unroll
            for (int mt = 0; mt < 4; ++mt) {
                uint32_t a[4];
                ldsm4(a, abase[mt] + bufoff + (uint32_t)((hb[mt] ^ (ks << 1)) << 4));
                mma16(acc[mt][0], a, bb0[0], bb0[1]);
                mma16(acc[mt][1], a, bb0[2], bb0[3]);
                mma16(acc[mt][2], a, bb1[0], bb1[1]);
                mma16(acc[mt][3], a, bb1[2], bb1[3]);
            }
        }

        if ((gc & 3) == 3) {
            // ---- epilogue for tile = bx + (gc>>2)*grid ----
            int tile = bx + (gc >> 2) * grid;
            float part[8];
            #pragma unroll
            for (int mt = 0; mt < 4; ++mt) {
                float p0 = 0.f, p1 = 0.f;
                #pragma unroll
                for (int nt = 0; nt < 4; ++nt) {
                    int l0 = warp_n * 32 + nt * 8 + tig * 2;
                    float w0 = w_s[l0], w1 = w_s[l0 + 1];
                    p0 += w0 * tanh_fast(acc[mt][nt][0]) + w1 * tanh_fast(acc[mt][nt][1]);
                    p1 += w0 * tanh_fast(acc[mt][nt][2]) + w1 * tanh_fast(acc[mt][nt][3]);
                    #pragma unroll
                    for (int i = 0; i < 4; i++) acc[mt][nt][i] = 0.0f;
                }
                part[mt * 2] = p0;
                part[mt * 2 + 1] = p1;
            }
            #pragma unroll
            for (int i = 0; i < 8; i++) {
                part[i] += __shfl_xor_sync(0xffffffffu, part[i], 1);
                part[i] += __shfl_xor_sync(0xffffffffu, part[i], 2);
            }
            if (tig == 0) {
                #pragma unroll
                for (int i = 0; i < 8; i++) {
                    int row = warp_m * 64 + (i >> 1) * 16 + (i & 1) * 8 + g;
                    atomicAdd(&sc_s[row], part[i]);
                }
            }
            __syncthreads();   // all atomicAdds visible
            if (tid < 64) {
                float s0 = sc_s[2 * tid];
                float s1 = sc_s[2 * tid + 1];
                sc_s[2 * tid] = 0.0f;
                sc_s[2 * tid + 1] = 0.0f;
                int P = tile * 64 + tid;            // global (b*T + t)
                int b = P >> 12;
                int t = P & 4095;
                float a0 = 1.0f / (1.0f + __expf(s1 - s0));
                out[((b * 2) + 0) * T_DIM + t] = a0;
                out[((b * 2) + 1) * T_DIM + t] = 1.0f - a0;
            }
        }
    }
}

extern "C" void kernel_launch(void* const* d_in, const int* in_sizes, int n_in,
                              void* d_out, int out_size) {
    const float* h1 = (const float*)d_in[0];
    const float* h2 = (const float*)d_in[1];
    const float* w  = (const float*)d_in[2];
    const float* v  = (const float*)d_in[3];
    float* out = (float*)d_out;

    cudaFuncSetAttribute(topo_attention_v4,
                         cudaFuncAttributeMaxDynamicSharedMemorySize, SMEM_BYTES);

    int nsm = 148;
    if (cudaDeviceGetAttribute(&nsm, cudaDevAttrMultiProcessorCount, 0) != cudaSuccess || nsm <= 0)
        nsm = 148;

    topo_attention_v4<<<2 * nsm, THREADS, SMEM_BYTES>>>(h1, h2, w, v, out);
}